// round 16
// baseline (speedup 1.0000x reference)
#include <cuda_runtime.h>
#include <cuda_fp16.h>
#include <cstdint>

#define HID    1024
#define FEAT   512
#define KCAT   1536
#define KEXT   4608          // 3 segments: hi | lo*1024 | hi/1024
#define N4H    4096
#define NBATCH 1024
#define NPREV  10
#define NPRED  20
#define TSTEPS 30
#define RMAX   2048
#define XROWS  (TSTEPS * NBATCH + NPRED * NBATCH)   // 51200

#define BM 128
#define BN 128
#define NKC 144              // 4608 / 32
#define STR 40               // padded row stride (halfs) for 32-half rows
#define TILE_A_HALFS (128 * STR)          // 5120
#define TILE_B_HALFS (128 * STR)          // 5120
#define BUFP_HALFS (TILE_A_HALFS + TILE_B_HALFS)   // 10240 per stage
#define NSTAGE 4
#define SMEM_BYTES (NSTAGE * BUFP_HALFS * 2)       // 81920

// ---------------- device globals ----------------
// W_ext: [n][ W_hi | W_hi/1024 | W_lo*1024 ], n = 4*j+gate
__device__ __half g_WB[(size_t)N4H * KEXT];
__device__ float  g_bperm[N4H];
// x splits: [xrow][ x_hi(512) | x_lo*1024(512) | x_hi/1024(512) ]
__device__ __half g_xs[(size_t)XROWS * KCAT];
// h splits: [r][ h_hi | h_lo*1024 | h_hi/1024 ] (1024 each)
__device__ __half g_h[(size_t)RMAX * 3 * HID];
__device__ float  g_ct[(size_t)HID * RMAX];      // transposed cell state [j][r]
__device__ float  g_hd[NPRED * RMAX];            // head partial dots

// ---------------- helpers ----------------
__device__ __forceinline__ uint32_t smem_u32(const void* p) {
    uint32_t a;
    asm("{ .reg .u64 t; cvta.to.shared.u64 t, %1; cvt.u32.u64 %0, t; }" : "=r"(a) : "l"(p));
    return a;
}
#define CP16(dst_u32, src_ptr) \
    asm volatile("cp.async.cg.shared.global [%0], [%1], 16;" :: "r"(dst_u32), "l"(src_ptr))
#define CP_COMMIT() asm volatile("cp.async.commit_group;" ::: "memory")
#define CP_WAIT(n)  asm volatile("cp.async.wait_group %0;" :: "n"(n) : "memory")

#define LDSM4(r0, r1, r2, r3, addr) \
    asm volatile("ldmatrix.sync.aligned.m8n8.x4.shared.b16 {%0,%1,%2,%3}, [%4];" \
        : "=r"(r0), "=r"(r1), "=r"(r2), "=r"(r3) : "r"(addr))

__device__ __forceinline__ void mma16(float* c, const uint32_t* a, const uint32_t* b) {
    asm volatile(
        "mma.sync.aligned.m16n8k16.row.col.f32.f16.f16.f32 "
        "{%0,%1,%2,%3}, {%4,%5,%6,%7}, {%8,%9}, {%0,%1,%2,%3};"
        : "+f"(c[0]), "+f"(c[1]), "+f"(c[2]), "+f"(c[3])
        : "r"(a[0]), "r"(a[1]), "r"(a[2]), "r"(a[3]), "r"(b[0]), "r"(b[1]));
}
// v -> hi (fp16), lo = rn((v-hi)*1024), sc = hi/1024 (exact shift)
__device__ __forceinline__ void split3(float v, __half& hi, __half& lo, __half& sc) {
    hi = __float2half_rn(v);
    float hf = __half2float(hi);
    lo = __float2half_rn((v - hf) * 1024.0f);
    sc = __float2half_rn(hf * (1.0f / 1024.0f));
}
// fast sigmoid: |rel err| ~1e-7, far below the 1.5e-5 pipeline noise floor
__device__ __forceinline__ float fsig(float z) {
    return __fdividef(1.0f, 1.0f + __expf(-z));
}

// ---------------- build: W transpose + gate-permute + fp16 3-way split ----------------
__global__ void k_build_w(const float* __restrict__ Wx, const float* __restrict__ Wh) {
    __shared__ float s[32][33];
    int c0 = blockIdx.x * 32;
    int k0 = blockIdx.y * 32;
    int tx = threadIdx.x, ty = threadIdx.y;
    int k = k0 + ty;
    const float* src = (k < FEAT) ? (Wx + (size_t)k * N4H + c0 + tx)
                                  : (Wh + (size_t)(k - FEAT) * N4H + c0 + tx);
    s[ty][tx] = *src;
    __syncthreads();
    int col = c0 + ty;
    int n = ((col & 1023) << 2) | (col >> 10);   // n = 4*j + gate
    __half hi, lo, sc;
    split3(s[tx][ty], hi, lo, sc);
    size_t base = (size_t)n * KEXT + (k0 + tx);
    g_WB[base]            = hi;
    g_WB[base + KCAT]     = sc;   // pairs with A_lo*1024
    g_WB[base + 2 * KCAT] = lo;   // pairs with A_hi/1024
}

// fused setup: x-split for all 50 timesteps + state zeroing + bias permute
__global__ void k_init(const float* __restrict__ real, const float* __restrict__ fake,
                       const float* __restrict__ b) {
    int idx = blockIdx.x * blockDim.x + threadIdx.x;
    if (idx < XROWS * FEAT / 4) {
        int e = idx * 4;
        int xrow = e >> 9, f = e & 511;
        const float* src;
        if (xrow < TSTEPS * NBATCH) {
            int t = xrow >> 10, r = xrow & 1023;
            src = real + ((size_t)r * TSTEPS + t) * FEAT + f;
        } else {
            int q = (xrow - TSTEPS * NBATCH) >> 10, r = xrow & 1023;
            src = fake + ((size_t)r * NPRED + q) * FEAT + f;
        }
        float4 v = *(const float4*)src;
        __half h[4], l[4], s[4];
        split3(v.x, h[0], l[0], s[0]); split3(v.y, h[1], l[1], s[1]);
        split3(v.z, h[2], l[2], s[2]); split3(v.w, h[3], l[3], s[3]);
        size_t base = (size_t)xrow * KCAT + f;
        *(uint2*)(g_xs + base)            = *(uint2*)h;
        *(uint2*)(g_xs + base + FEAT)     = *(uint2*)l;
        *(uint2*)(g_xs + base + 2 * FEAT) = *(uint2*)s;
    }
    {
        const int n1 = RMAX * 3 * HID / 8;
        const int n2 = HID * RMAX / 4;
        const int n3 = NPRED * RMAX / 4;
        if (idx < n1)                 ((uint4*)g_h)[idx] = make_uint4(0u, 0u, 0u, 0u);
        else if (idx < n1 + n2)       ((float4*)g_ct)[idx - n1] = make_float4(0.f, 0.f, 0.f, 0.f);
        else if (idx < n1 + n2 + n3)  ((float4*)g_hd)[idx - n1 - n2] = make_float4(0.f, 0.f, 0.f, 0.f);
    }
    if (idx < N4H) g_bperm[idx] = b[((idx & 3) << 10) | (idx >> 2)];
}

__global__ void k_fork() {
    int idx = blockIdx.x * blockDim.x + threadIdx.x;
    if (idx < NBATCH * 384) {
        int r = idx / 384, q = idx % 384;
        *(uint4*)(g_h + (size_t)(NBATCH + r) * 3 * HID + 8 * q) =
            *(uint4*)(g_h + (size_t)r * 3 * HID + 8 * q);
    }
    if (idx < NBATCH * HID) {
        int j = idx >> 10, r = idx & (NBATCH - 1);
        g_ct[(size_t)j * RMAX + NBATCH + r] = g_ct[(size_t)j * RMAX + r];
    }
}

// ---------------- fused LSTM step ----------------
// CTA: 128 rows x 128 permuted-n; 8 warps 2(M)x4(N), warp tile 64x32
// (R9's proven fragment pattern) on the R10/R14/R15-proven 4-stage cadence:
// load(kc+2) -> commit -> wait(2) -> barrier -> compute(kc).
__global__ void __launch_bounds__(256, 2) k_step(int t, const float* __restrict__ w2) {
    extern __shared__ __half sm[];
    const uint32_t sb = smem_u32(sm);
    const int tid  = threadIdx.x;
    const int lane = tid & 31, wid = tid >> 5;
    const int g    = lane >> 2, tig = lane & 3;
    const int wm   = (wid >> 2) * 64;
    const int wn   = (wid & 3) * 32;
    const int bm = blockIdx.y, bn = blockIdx.x;

    const int xbase = (bm < 8) ? (t * NBATCH + bm * BM)
                               : (TSTEPS * NBATCH + (t - NPREV) * NBATCH + (bm - 8) * BM);
    const __half* Xg = g_xs + (size_t)xbase * KCAT;
    const __half* Hg = g_h + (size_t)bm * BM * 3 * HID;
    const __half* Bg = g_WB + (size_t)bn * BN * KEXT;

    float acc[4][4][4];
#pragma unroll
    for (int mt = 0; mt < 4; mt++)
#pragma unroll
        for (int nt = 0; nt < 4; nt++)
#pragma unroll
            for (int e = 0; e < 4; e++) acc[mt][nt][e] = 0.f;

    // ---- per-thread loop-invariant load offsets ----
    // A and B both: 128 rows x 32 halfs, 2 CP16 per thread each.
    const int r0 = tid >> 2,         c8 = (tid & 3) * 8;
    const int r1 = (tid + 256) >> 2;                       // (tid+256)&3 == tid&3
    const uint32_t dstA0 = sb + (r0 * STR + c8) * 2;
    const uint32_t dstA1 = sb + (r1 * STR + c8) * 2;
    const uint32_t dstB0 = sb + (TILE_A_HALFS + r0 * STR + c8) * 2;
    const uint32_t dstB1 = sb + (TILE_A_HALFS + r1 * STR + c8) * 2;
    const int offXA0 = r0 * KCAT + c8,    offXA1 = r1 * KCAT + c8;
    const int offHA0 = r0 * 3 * HID + c8, offHA1 = r1 * 3 * HID + c8;
    const __half* srcB0 = Bg + (size_t)r0 * KEXT + c8;
    const __half* srcB1 = Bg + (size_t)r1 * KEXT + c8;

    auto load_tile = [&](int kc, int stage) {
        const uint32_t sofs = stage * (BUFP_HALFS * 2);
        int k0 = 32 * kc;
        int seg = (k0 >= 2 * KCAT) ? 2 : ((k0 >= KCAT) ? 1 : 0);
        int kk0 = k0 - seg * KCAT;
        const __half* A0;
        const __half* A1;
        if (kk0 < FEAT) {
            const __half* As = Xg + seg * FEAT + kk0;
            A0 = As + offXA0; A1 = As + offXA1;
        } else {
            const __half* As = Hg + seg * HID + (kk0 - FEAT);
            A0 = As + offHA0; A1 = As + offHA1;
        }
        CP16(dstA0 + sofs, A0);
        CP16(dstA1 + sofs, A1);
        CP16(dstB0 + sofs, srcB0 + k0);
        CP16(dstB1 + sofs, srcB1 + k0);
    };

    // per-lane ldmatrix row offsets (halfs); 16-row x4 form for A and B
    const int a_off = (wm + (lane & 15)) * STR + ((lane >> 4) << 3);
    const int b_off = (wn + (lane & 15)) * STR + ((lane >> 4) << 3);

    load_tile(0, 0);
    CP_COMMIT();
    load_tile(1, 1);
    CP_COMMIT();

    for (int kc = 0; kc < NKC; kc++) {
        if (kc + 2 < NKC) {
            load_tile(kc + 2, (kc + 2) & 3);
            CP_COMMIT();
            CP_WAIT(2);
        } else if (kc + 1 < NKC) {
            CP_WAIT(1);
        } else {
            CP_WAIT(0);
        }
        __syncthreads();

        const uint32_t bufb = sb + (kc & 3) * (BUFP_HALFS * 2);
        const uint32_t abase = bufb + a_off * 2;
        const uint32_t bbase = bufb + (TILE_A_HALFS + b_off) * 2;

#pragma unroll
        for (int k16 = 0; k16 < 32; k16 += 16) {
            uint32_t af[4][4], bf[4][2];
#pragma unroll
            for (int mt = 0; mt < 4; mt++)
                LDSM4(af[mt][0], af[mt][1], af[mt][2], af[mt][3],
                      abase + (mt * (16 * STR) + k16) * 2);
#pragma unroll
            for (int np = 0; np < 2; np++)   // 16 n-rows per LDSM4 = nt pair (2np, 2np+1)
                LDSM4(bf[2 * np][0], bf[2 * np + 1][0],
                      bf[2 * np][1], bf[2 * np + 1][1],
                      bbase + (np * (16 * STR) + k16) * 2);
#pragma unroll
            for (int mt = 0; mt < 4; mt++)
#pragma unroll
                for (int nt = 0; nt < 4; nt++)
                    mma16(acc[mt][nt], af[mt], bf[nt]);
        }
    }

    // ---- fused gate epilogue + head partials ----
    // staging uses first 15360 halfs (stages 0-1); last compute read stage 3 — disjoint
    __half* hhi = sm;
    __half* hlo = sm + TILE_A_HALFS;
    __half* hsc = sm + 2 * TILE_A_HALFS;
    const bool do_head = (t >= NPREV);
#pragma unroll
    for (int mt = 0; mt < 4; mt++) {
        float hsum = 0.f;
        int rl_head = 0;
#pragma unroll
        for (int nt = 0; nt < 4; nt++) {
            float* v4 = acc[mt][nt];
            bool odd = (tig & 1);
            float x = odd ? v4[0] : v4[2];
            float y = odd ? v4[1] : v4[3];
            float p = __shfl_xor_sync(0xffffffffu, x, 1);
            float q = __shfl_xor_sync(0xffffffffu, y, 1);
            float zi, zf, zg, zo; int ro;
            if (odd) { zi = p;     zf = q;     zg = v4[2]; zo = v4[3]; ro = 8; }
            else     { zi = v4[0]; zf = v4[1]; zg = p;     zo = q;     ro = 0; }
            int jl = (wn >> 2) + nt * 2 + (tig >> 1);     // 0..31
            int j  = bn * 32 + jl;
            float4 bb = *(const float4*)(g_bperm + 4 * j);
            zi += bb.x; zf += bb.y; zg += bb.z; zo += bb.w;
            int rl  = wm + mt * 16 + g + ro;
            int row = bm * BM + rl;
            float ig = fsig(zi);
            float fg = fsig(zf);
            float gg = tanhf(zg);
            float og = fsig(zo);
            float cc = fg * g_ct[(size_t)j * RMAX + row] + ig * gg;
            g_ct[(size_t)j * RMAX + row] = cc;
            float hv = og * tanhf(cc);
            if (do_head) hsum += hv * w2[j];
            rl_head = rl;
            __half hh, hl, hs;
            split3(hv, hh, hl, hs);
            hhi[rl * STR + jl] = hh;
            hlo[rl * STR + jl] = hl;
            hsc[rl * STR + jl] = hs;
        }
        if (do_head) {
            // tig{0,2} own row g; tig{1,3} own row g+8. XOR-2 merges j-halves of same row.
            hsum += __shfl_xor_sync(0xffffffffu, hsum, 2);
            if (tig < 2)
                atomicAdd(&g_hd[(t - NPREV) * RMAX + bm * BM + rl_head], hsum);
        }
    }
    __syncthreads();
    // coalesced h writeback: 3 segments x 128 rows x 32 halfs = 1536 uint4
#pragma unroll
    for (int i = 0; i < 6; i++) {
        int lin = tid + i * 256;              // 0..1535
        int region = lin >> 9, rem = lin & 511;
        int r = rem >> 2, cc8 = (rem & 3) * 8;
        uint4 v = *(uint4*)(sm + region * TILE_A_HALFS + r * STR + cc8);
        *(uint4*)(g_h + (size_t)(bm * BM + r) * 3 * HID +
                  region * HID + bn * 32 + cc8) = v;
    }
}

// ---------------- final head: tanh chain over accumulated dots ----------------
__global__ __launch_bounds__(256) void k_headfin(const float* __restrict__ b2,
                                                 const float* __restrict__ w3,
                                                 const float* __restrict__ b3,
                                                 const float* __restrict__ w4,
                                                 const float* __restrict__ b4,
                                                 float* __restrict__ out) {
    int idx = blockIdx.x * blockDim.x + threadIdx.x;
    if (idx >= NPRED * RMAX) return;
    int k = idx / RMAX, r = idx % RMAX;
    float x = tanhf(g_hd[k * RMAX + r] + b2[0]);
    x = tanhf(x * w3[0] + b3[0]);
    x = tanhf(x * w4[0] + b4[0]);
    int pos = (r < NBATCH) ? r * NPRED + k
                           : NBATCH * NPRED + (r - NBATCH) * NPRED + k;
    out[pos] = x;
}

extern "C" void kernel_launch(void* const* d_in, const int* in_sizes, int n_in,
                              void* d_out, int out_size) {
    const float* real = (const float*)d_in[0];
    const float* fake = (const float*)d_in[1];
    const float* Wx   = (const float*)d_in[2];
    const float* Wh   = (const float*)d_in[3];
    const float* b    = (const float*)d_in[4];
    const float* w2   = (const float*)d_in[5];
    const float* b2   = (const float*)d_in[6];
    const float* w3   = (const float*)d_in[7];
    const float* b3   = (const float*)d_in[8];
    const float* w4   = (const float*)d_in[9];
    const float* b4   = (const float*)d_in[10];
    float* out = (float*)d_out;

    cudaFuncSetAttribute(k_step, cudaFuncAttributeMaxDynamicSharedMemorySize, SMEM_BYTES);

    {
        dim3 bd(32, 32), gd(N4H / 32, KCAT / 32);
        k_build_w<<<gd, bd>>>(Wx, Wh);
    }
    k_init<<<(XROWS * FEAT / 4 + 255) / 256, 256>>>(real, fake, b);

    for (int t = 0; t < TSTEPS; t++) {
        int R = (t < NPREV) ? NBATCH : RMAX;
        if (t == NPREV) k_fork<<<(NBATCH * HID + 255) / 256, 256>>>();
        dim3 grid(N4H / BN, R / BM);
        k_step<<<grid, 256, SMEM_BYTES>>>(t, w2);
    }
    k_headfin<<<(NPRED * RMAX + 255) / 256, 256>>>(b2, w3, b3, w4, b4, out);
}

// round 17
// speedup vs baseline: 1.0342x; 1.0342x over previous
#include <cuda_runtime.h>
#include <cuda_fp16.h>
#include <cstdint>

#define HID    1024
#define FEAT   512
#define KCAT   1536
#define KEXT   4608          // 3 segments: hi | lo*1024 | hi/1024
#define N4H    4096
#define NBATCH 1024
#define NPREV  10
#define NPRED  20
#define TSTEPS 30
#define RMAX   2048
#define XROWS  (TSTEPS * NBATCH + NPRED * NBATCH)   // 51200

#define BM 128
#define NKC 144              // 4608 / 32
#define STR 40               // padded row stride (halfs) for 32-half rows
#define TILE_A_HALFS (128 * STR)          // 5120
// BN=64 variant
#define TILE_B64_HALFS (64 * STR)         // 2560
#define BUF64_HALFS (TILE_A_HALFS + TILE_B64_HALFS)   // 7680
#define SMEM64_BYTES (4 * BUF64_HALFS * 2)            // 61440
// BN=128 variant
#define TILE_B128_HALFS (128 * STR)       // 5120
#define BUF128_HALFS (TILE_A_HALFS + TILE_B128_HALFS) // 10240
#define SMEM128_BYTES (4 * BUF128_HALFS * 2)          // 81920

// ---------------- device globals ----------------
__device__ __half g_WB[(size_t)N4H * KEXT];
__device__ float  g_bperm[N4H];
__device__ __half g_xs[(size_t)XROWS * KCAT];
__device__ __half g_h[(size_t)RMAX * 3 * HID];
__device__ float  g_ct[(size_t)HID * RMAX];
__device__ float  g_hd[NPRED * RMAX];

// ---------------- helpers ----------------
__device__ __forceinline__ uint32_t smem_u32(const void* p) {
    uint32_t a;
    asm("{ .reg .u64 t; cvta.to.shared.u64 t, %1; cvt.u32.u64 %0, t; }" : "=r"(a) : "l"(p));
    return a;
}
#define CP16(dst_u32, src_ptr) \
    asm volatile("cp.async.cg.shared.global [%0], [%1], 16;" :: "r"(dst_u32), "l"(src_ptr))
#define CP_COMMIT() asm volatile("cp.async.commit_group;" ::: "memory")
#define CP_WAIT(n)  asm volatile("cp.async.wait_group %0;" :: "n"(n) : "memory")

#define LDSM4(r0, r1, r2, r3, addr) \
    asm volatile("ldmatrix.sync.aligned.m8n8.x4.shared.b16 {%0,%1,%2,%3}, [%4];" \
        : "=r"(r0), "=r"(r1), "=r"(r2), "=r"(r3) : "r"(addr))

__device__ __forceinline__ void mma16(float* c, const uint32_t* a, const uint32_t* b) {
    asm volatile(
        "mma.sync.aligned.m16n8k16.row.col.f32.f16.f16.f32 "
        "{%0,%1,%2,%3}, {%4,%5,%6,%7}, {%8,%9}, {%0,%1,%2,%3};"
        : "+f"(c[0]), "+f"(c[1]), "+f"(c[2]), "+f"(c[3])
        : "r"(a[0]), "r"(a[1]), "r"(a[2]), "r"(a[3]), "r"(b[0]), "r"(b[1]));
}
__device__ __forceinline__ void split3(float v, __half& hi, __half& lo, __half& sc) {
    hi = __float2half_rn(v);
    float hf = __half2float(hi);
    lo = __float2half_rn((v - hf) * 1024.0f);
    sc = __float2half_rn(hf * (1.0f / 1024.0f));
}
__device__ __forceinline__ float fsig(float z) {
    return __fdividef(1.0f, 1.0f + __expf(-z));
}

// ---------------- build: W transpose + gate-permute + fp16 3-way split ----------------
__global__ void k_build_w(const float* __restrict__ Wx, const float* __restrict__ Wh) {
    __shared__ float s[32][33];
    int c0 = blockIdx.x * 32;
    int k0 = blockIdx.y * 32;
    int tx = threadIdx.x, ty = threadIdx.y;
    int k = k0 + ty;
    const float* src = (k < FEAT) ? (Wx + (size_t)k * N4H + c0 + tx)
                                  : (Wh + (size_t)(k - FEAT) * N4H + c0 + tx);
    s[ty][tx] = *src;
    __syncthreads();
    int col = c0 + ty;
    int n = ((col & 1023) << 2) | (col >> 10);   // n = 4*j + gate
    __half hi, lo, sc;
    split3(s[tx][ty], hi, lo, sc);
    size_t base = (size_t)n * KEXT + (k0 + tx);
    g_WB[base]            = hi;
    g_WB[base + KCAT]     = sc;
    g_WB[base + 2 * KCAT] = lo;
}

// fused setup: x-split for all 50 timesteps + state zeroing + bias permute
__global__ void k_init(const float* __restrict__ real, const float* __restrict__ fake,
                       const float* __restrict__ b) {
    int idx = blockIdx.x * blockDim.x + threadIdx.x;
    if (idx < XROWS * FEAT / 4) {
        int e = idx * 4;
        int xrow = e >> 9, f = e & 511;
        const float* src;
        if (xrow < TSTEPS * NBATCH) {
            int t = xrow >> 10, r = xrow & 1023;
            src = real + ((size_t)r * TSTEPS + t) * FEAT + f;
        } else {
            int q = (xrow - TSTEPS * NBATCH) >> 10, r = xrow & 1023;
            src = fake + ((size_t)r * NPRED + q) * FEAT + f;
        }
        float4 v = *(const float4*)src;
        __half h[4], l[4], s[4];
        split3(v.x, h[0], l[0], s[0]); split3(v.y, h[1], l[1], s[1]);
        split3(v.z, h[2], l[2], s[2]); split3(v.w, h[3], l[3], s[3]);
        size_t base = (size_t)xrow * KCAT + f;
        *(uint2*)(g_xs + base)            = *(uint2*)h;
        *(uint2*)(g_xs + base + FEAT)     = *(uint2*)l;
        *(uint2*)(g_xs + base + 2 * FEAT) = *(uint2*)s;
    }
    {
        const int n1 = RMAX * 3 * HID / 8;
        const int n2 = HID * RMAX / 4;
        const int n3 = NPRED * RMAX / 4;
        if (idx < n1)                 ((uint4*)g_h)[idx] = make_uint4(0u, 0u, 0u, 0u);
        else if (idx < n1 + n2)       ((float4*)g_ct)[idx - n1] = make_float4(0.f, 0.f, 0.f, 0.f);
        else if (idx < n1 + n2 + n3)  ((float4*)g_hd)[idx - n1 - n2] = make_float4(0.f, 0.f, 0.f, 0.f);
    }
    if (idx < N4H) g_bperm[idx] = b[((idx & 3) << 10) | (idx >> 2)];
}

__global__ void k_fork() {
    int idx = blockIdx.x * blockDim.x + threadIdx.x;
    if (idx < NBATCH * 384) {
        int r = idx / 384, q = idx % 384;
        *(uint4*)(g_h + (size_t)(NBATCH + r) * 3 * HID + 8 * q) =
            *(uint4*)(g_h + (size_t)r * 3 * HID + 8 * q);
    }
    if (idx < NBATCH * HID) {
        int j = idx >> 10, r = idx & (NBATCH - 1);
        g_ct[(size_t)j * RMAX + NBATCH + r] = g_ct[(size_t)j * RMAX + r];
    }
}

// ================= BN=64 step (verbatim R15 pass) — used for FULL steps =================
__global__ void __launch_bounds__(256, 3) k_step64(int t, const float* __restrict__ w2) {
    extern __shared__ __half sm[];
    const uint32_t sb = smem_u32(sm);
    const int tid  = threadIdx.x;
    const int lane = tid & 31, wid = tid >> 5;
    const int g    = lane >> 2, tig = lane & 3;
    const int wm   = (wid >> 2) * 64;
    const int wn   = (wid & 3) * 16;
    const int bm = blockIdx.y, bn = blockIdx.x;

    const int xbase = (bm < 8) ? (t * NBATCH + bm * BM)
                               : (TSTEPS * NBATCH + (t - NPREV) * NBATCH + (bm - 8) * BM);
    const __half* Xg = g_xs + (size_t)xbase * KCAT;
    const __half* Hg = g_h + (size_t)bm * BM * 3 * HID;
    const __half* Bg = g_WB + (size_t)bn * 64 * KEXT;

    float acc[4][2][4];
#pragma unroll
    for (int mt = 0; mt < 4; mt++)
#pragma unroll
        for (int nt = 0; nt < 2; nt++)
#pragma unroll
            for (int e = 0; e < 4; e++) acc[mt][nt][e] = 0.f;

    const int rA0 = tid >> 2,            cA0 = (tid & 3) * 8;
    const int rA1 = (tid + 256) >> 2,    cA1 = (tid & 3) * 8;
    const uint32_t dstA0 = sb + (rA0 * STR + cA0) * 2;
    const uint32_t dstA1 = sb + (rA1 * STR + cA1) * 2;
    const int offXA0 = rA0 * KCAT + cA0,     offXA1 = rA1 * KCAT + cA1;
    const int offHA0 = rA0 * 3 * HID + cA0,  offHA1 = rA1 * 3 * HID + cA1;
    const int rB = tid >> 2, cB = (tid & 3) * 8;
    const uint32_t dstB = sb + (TILE_A_HALFS + rB * STR + cB) * 2;
    const __half* srcB0 = Bg + (size_t)rB * KEXT + cB;

    auto load_tile = [&](int kc, int stage) {
        const uint32_t sofs = stage * (BUF64_HALFS * 2);
        int k0 = 32 * kc;
        int seg = (k0 >= 2 * KCAT) ? 2 : ((k0 >= KCAT) ? 1 : 0);
        int kk0 = k0 - seg * KCAT;
        const __half* A0;
        const __half* A1;
        if (kk0 < FEAT) {
            const __half* As = Xg + seg * FEAT + kk0;
            A0 = As + offXA0; A1 = As + offXA1;
        } else {
            const __half* As = Hg + seg * HID + (kk0 - FEAT);
            A0 = As + offHA0; A1 = As + offHA1;
        }
        CP16(dstA0 + sofs, A0);
        CP16(dstA1 + sofs, A1);
        CP16(dstB + sofs, srcB0 + k0);
    };

    const int a_off = (wm + (lane & 15)) * STR + ((lane >> 4) << 3);
    const int b_off = (wn + (lane & 15)) * STR + ((lane >> 4) << 3);

    load_tile(0, 0);
    CP_COMMIT();
    load_tile(1, 1);
    CP_COMMIT();

    for (int kc = 0; kc < NKC; kc++) {
        if (kc + 2 < NKC) {
            load_tile(kc + 2, (kc + 2) & 3);
            CP_COMMIT();
            CP_WAIT(2);
        } else if (kc + 1 < NKC) {
            CP_WAIT(1);
        } else {
            CP_WAIT(0);
        }
        __syncthreads();

        const uint32_t bufb = sb + (kc & 3) * (BUF64_HALFS * 2);
        const uint32_t abase = bufb + a_off * 2;
        const uint32_t bbase = bufb + (TILE_A_HALFS + b_off) * 2;

#pragma unroll
        for (int k16 = 0; k16 < 32; k16 += 16) {
            uint32_t af[4][4], bf[2][2];
#pragma unroll
            for (int mt = 0; mt < 4; mt++)
                LDSM4(af[mt][0], af[mt][1], af[mt][2], af[mt][3],
                      abase + (mt * (16 * STR) + k16) * 2);
            LDSM4(bf[0][0], bf[1][0], bf[0][1], bf[1][1], bbase + k16 * 2);
#pragma unroll
            for (int mt = 0; mt < 4; mt++)
#pragma unroll
                for (int nt = 0; nt < 2; nt++)
                    mma16(acc[mt][nt], af[mt], bf[nt]);
        }
    }

    __half* hhi = sm;
    __half* hlo = sm + TILE_A_HALFS;
    __half* hsc = sm + 2 * TILE_A_HALFS;
    const bool do_head = (t >= NPREV);
#pragma unroll
    for (int mt = 0; mt < 4; mt++) {
        float hsum = 0.f;
        int rl_head = 0;
#pragma unroll
        for (int nt = 0; nt < 2; nt++) {
            float* v4 = acc[mt][nt];
            bool odd = (tig & 1);
            float x = odd ? v4[0] : v4[2];
            float y = odd ? v4[1] : v4[3];
            float p = __shfl_xor_sync(0xffffffffu, x, 1);
            float q = __shfl_xor_sync(0xffffffffu, y, 1);
            float zi, zf, zg, zo; int ro;
            if (odd) { zi = p;     zf = q;     zg = v4[2]; zo = v4[3]; ro = 8; }
            else     { zi = v4[0]; zf = v4[1]; zg = p;     zo = q;     ro = 0; }
            int jl = (wn >> 2) + nt * 2 + (tig >> 1);     // 0..15
            int j  = bn * 16 + jl;
            float4 bb = *(const float4*)(g_bperm + 4 * j);
            zi += bb.x; zf += bb.y; zg += bb.z; zo += bb.w;
            int rl  = wm + mt * 16 + g + ro;
            int row = bm * BM + rl;
            float ig = fsig(zi);
            float fg = fsig(zf);
            float gg = tanhf(zg);
            float og = fsig(zo);
            float cc = fg * g_ct[(size_t)j * RMAX + row] + ig * gg;
            g_ct[(size_t)j * RMAX + row] = cc;
            float hv = og * tanhf(cc);
            if (do_head) hsum += hv * w2[j];
            rl_head = rl;
            __half hh, hl, hs;
            split3(hv, hh, hl, hs);
            hhi[rl * STR + jl] = hh;
            hlo[rl * STR + jl] = hl;
            hsc[rl * STR + jl] = hs;
        }
        if (do_head) {
            hsum += __shfl_xor_sync(0xffffffffu, hsum, 2);
            if (tig < 2)
                atomicAdd(&g_hd[(t - NPREV) * RMAX + bm * BM + rl_head], hsum);
        }
    }
    __syncthreads();
#pragma unroll
    for (int i = 0; i < 3; i++) {
        int lin = tid + i * 256;
        int region = lin >> 8, rem = lin & 255;
        int r = rem >> 1, c8 = (rem & 1) * 8;
        uint4 v = *(uint4*)(sm + region * TILE_A_HALFS + r * STR + c8);
        *(uint4*)(g_h + (size_t)(bm * BM + r) * 3 * HID +
                  region * HID + bn * 16 + c8) = v;
    }
}

// ================= BN=128 step (verbatim R16 pass) — used for PREFIX steps =================
__global__ void __launch_bounds__(256, 2) k_step128(int t, const float* __restrict__ w2) {
    extern __shared__ __half sm[];
    const uint32_t sb = smem_u32(sm);
    const int tid  = threadIdx.x;
    const int lane = tid & 31, wid = tid >> 5;
    const int g    = lane >> 2, tig = lane & 3;
    const int wm   = (wid >> 2) * 64;
    const int wn   = (wid & 3) * 32;
    const int bm = blockIdx.y, bn = blockIdx.x;

    const int xbase = (bm < 8) ? (t * NBATCH + bm * BM)
                               : (TSTEPS * NBATCH + (t - NPREV) * NBATCH + (bm - 8) * BM);
    const __half* Xg = g_xs + (size_t)xbase * KCAT;
    const __half* Hg = g_h + (size_t)bm * BM * 3 * HID;
    const __half* Bg = g_WB + (size_t)bn * 128 * KEXT;

    float acc[4][4][4];
#pragma unroll
    for (int mt = 0; mt < 4; mt++)
#pragma unroll
        for (int nt = 0; nt < 4; nt++)
#pragma unroll
            for (int e = 0; e < 4; e++) acc[mt][nt][e] = 0.f;

    const int r0 = tid >> 2,         c8 = (tid & 3) * 8;
    const int r1 = (tid + 256) >> 2;
    const uint32_t dstA0 = sb + (r0 * STR + c8) * 2;
    const uint32_t dstA1 = sb + (r1 * STR + c8) * 2;
    const uint32_t dstB0 = sb + (TILE_A_HALFS + r0 * STR + c8) * 2;
    const uint32_t dstB1 = sb + (TILE_A_HALFS + r1 * STR + c8) * 2;
    const int offXA0 = r0 * KCAT + c8,    offXA1 = r1 * KCAT + c8;
    const int offHA0 = r0 * 3 * HID + c8, offHA1 = r1 * 3 * HID + c8;
    const __half* srcB0 = Bg + (size_t)r0 * KEXT + c8;
    const __half* srcB1 = Bg + (size_t)r1 * KEXT + c8;

    auto load_tile = [&](int kc, int stage) {
        const uint32_t sofs = stage * (BUF128_HALFS * 2);
        int k0 = 32 * kc;
        int seg = (k0 >= 2 * KCAT) ? 2 : ((k0 >= KCAT) ? 1 : 0);
        int kk0 = k0 - seg * KCAT;
        const __half* A0;
        const __half* A1;
        if (kk0 < FEAT) {
            const __half* As = Xg + seg * FEAT + kk0;
            A0 = As + offXA0; A1 = As + offXA1;
        } else {
            const __half* As = Hg + seg * HID + (kk0 - FEAT);
            A0 = As + offHA0; A1 = As + offHA1;
        }
        CP16(dstA0 + sofs, A0);
        CP16(dstA1 + sofs, A1);
        CP16(dstB0 + sofs, srcB0 + k0);
        CP16(dstB1 + sofs, srcB1 + k0);
    };

    const int a_off = (wm + (lane & 15)) * STR + ((lane >> 4) << 3);
    const int b_off = (wn + (lane & 15)) * STR + ((lane >> 4) << 3);

    load_tile(0, 0);
    CP_COMMIT();
    load_tile(1, 1);
    CP_COMMIT();

    for (int kc = 0; kc < NKC; kc++) {
        if (kc + 2 < NKC) {
            load_tile(kc + 2, (kc + 2) & 3);
            CP_COMMIT();
            CP_WAIT(2);
        } else if (kc + 1 < NKC) {
            CP_WAIT(1);
        } else {
            CP_WAIT(0);
        }
        __syncthreads();

        const uint32_t bufb = sb + (kc & 3) * (BUF128_HALFS * 2);
        const uint32_t abase = bufb + a_off * 2;
        const uint32_t bbase = bufb + (TILE_A_HALFS + b_off) * 2;

#pragma unroll
        for (int k16 = 0; k16 < 32; k16 += 16) {
            uint32_t af[4][4], bf[4][2];
#pragma unroll
            for (int mt = 0; mt < 4; mt++)
                LDSM4(af[mt][0], af[mt][1], af[mt][2], af[mt][3],
                      abase + (mt * (16 * STR) + k16) * 2);
#pragma unroll
            for (int np = 0; np < 2; np++)
                LDSM4(bf[2 * np][0], bf[2 * np + 1][0],
                      bf[2 * np][1], bf[2 * np + 1][1],
                      bbase + (np * (16 * STR) + k16) * 2);
#pragma unroll
            for (int mt = 0; mt < 4; mt++)
#pragma unroll
                for (int nt = 0; nt < 4; nt++)
                    mma16(acc[mt][nt], af[mt], bf[nt]);
        }
    }

    __half* hhi = sm;
    __half* hlo = sm + TILE_A_HALFS;
    __half* hsc = sm + 2 * TILE_A_HALFS;
    const bool do_head = (t >= NPREV);
#pragma unroll
    for (int mt = 0; mt < 4; mt++) {
        float hsum = 0.f;
        int rl_head = 0;
#pragma unroll
        for (int nt = 0; nt < 4; nt++) {
            float* v4 = acc[mt][nt];
            bool odd = (tig & 1);
            float x = odd ? v4[0] : v4[2];
            float y = odd ? v4[1] : v4[3];
            float p = __shfl_xor_sync(0xffffffffu, x, 1);
            float q = __shfl_xor_sync(0xffffffffu, y, 1);
            float zi, zf, zg, zo; int ro;
            if (odd) { zi = p;     zf = q;     zg = v4[2]; zo = v4[3]; ro = 8; }
            else     { zi = v4[0]; zf = v4[1]; zg = p;     zo = q;     ro = 0; }
            int jl = (wn >> 2) + nt * 2 + (tig >> 1);     // 0..31
            int j  = bn * 32 + jl;
            float4 bb = *(const float4*)(g_bperm + 4 * j);
            zi += bb.x; zf += bb.y; zg += bb.z; zo += bb.w;
            int rl  = wm + mt * 16 + g + ro;
            int row = bm * BM + rl;
            float ig = fsig(zi);
            float fg = fsig(zf);
            float gg = tanhf(zg);
            float og = fsig(zo);
            float cc = fg * g_ct[(size_t)j * RMAX + row] + ig * gg;
            g_ct[(size_t)j * RMAX + row] = cc;
            float hv = og * tanhf(cc);
            if (do_head) hsum += hv * w2[j];
            rl_head = rl;
            __half hh, hl, hs;
            split3(hv, hh, hl, hs);
            hhi[rl * STR + jl] = hh;
            hlo[rl * STR + jl] = hl;
            hsc[rl * STR + jl] = hs;
        }
        if (do_head) {
            hsum += __shfl_xor_sync(0xffffffffu, hsum, 2);
            if (tig < 2)
                atomicAdd(&g_hd[(t - NPREV) * RMAX + bm * BM + rl_head], hsum);
        }
    }
    __syncthreads();
#pragma unroll
    for (int i = 0; i < 6; i++) {
        int lin = tid + i * 256;
        int region = lin >> 9, rem = lin & 511;
        int r = rem >> 2, cc8 = (rem & 3) * 8;
        uint4 v = *(uint4*)(sm + region * TILE_A_HALFS + r * STR + cc8);
        *(uint4*)(g_h + (size_t)(bm * BM + r) * 3 * HID +
                  region * HID + bn * 32 + cc8) = v;
    }
}

// ---------------- final head: tanh chain over accumulated dots ----------------
__global__ __launch_bounds__(256) void k_headfin(const float* __restrict__ b2,
                                                 const float* __restrict__ w3,
                                                 const float* __restrict__ b3,
                                                 const float* __restrict__ w4,
                                                 const float* __restrict__ b4,
                                                 float* __restrict__ out) {
    int idx = blockIdx.x * blockDim.x + threadIdx.x;
    if (idx >= NPRED * RMAX) return;
    int k = idx / RMAX, r = idx % RMAX;
    float x = tanhf(g_hd[k * RMAX + r] + b2[0]);
    x = tanhf(x * w3[0] + b3[0]);
    x = tanhf(x * w4[0] + b4[0]);
    int pos = (r < NBATCH) ? r * NPRED + k
                           : NBATCH * NPRED + (r - NBATCH) * NPRED + k;
    out[pos] = x;
}

extern "C" void kernel_launch(void* const* d_in, const int* in_sizes, int n_in,
                              void* d_out, int out_size) {
    const float* real = (const float*)d_in[0];
    const float* fake = (const float*)d_in[1];
    const float* Wx   = (const float*)d_in[2];
    const float* Wh   = (const float*)d_in[3];
    const float* b    = (const float*)d_in[4];
    const float* w2   = (const float*)d_in[5];
    const float* b2   = (const float*)d_in[6];
    const float* w3   = (const float*)d_in[7];
    const float* b3   = (const float*)d_in[8];
    const float* w4   = (const float*)d_in[9];
    const float* b4   = (const float*)d_in[10];
    float* out = (float*)d_out;

    cudaFuncSetAttribute(k_step64, cudaFuncAttributeMaxDynamicSharedMemorySize, SMEM64_BYTES);
    cudaFuncSetAttribute(k_step128, cudaFuncAttributeMaxDynamicSharedMemorySize, SMEM128_BYTES);

    {
        dim3 bd(32, 32), gd(N4H / 32, KCAT / 32);
        k_build_w<<<gd, bd>>>(Wx, Wh);
    }
    k_init<<<(XROWS * FEAT / 4 + 255) / 256, 256>>>(real, fake, b);

    for (int t = 0; t < TSTEPS; t++) {
        if (t == NPREV) k_fork<<<(NBATCH * HID + 255) / 256, 256>>>();
        if (t < NPREV) {
            dim3 grid(N4H / 128, NBATCH / BM);      // (32, 8)
            k_step128<<<grid, 256, SMEM128_BYTES>>>(t, w2);
        } else {
            dim3 grid(N4H / 64, RMAX / BM);         // (64, 16)
            k_step64<<<grid, 256, SMEM64_BYTES>>>(t, w2);
        }
    }
    k_headfin<<<(NPRED * RMAX + 255) / 256, 256>>>(b2, w3, b3, w4, b4, out);
}